// round 1
// baseline (speedup 1.0000x reference)
#include <cuda_runtime.h>

#define Nn 100000
#define Ee 1600000

// ---------------- scratch (device globals; allocation-free) ----------------
__device__ float g_feat1[Nn * 128];   // layer1 projected features [N,4,32]
__device__ float g_el1[Nn * 4];
__device__ float g_er1[Nn * 4];
__device__ float g_expe1[Ee * 4];     // exp(leaky(el+er)) per edge/head
__device__ float g_denom1[Nn * 4];    // softmax denominators
__device__ float g_out1[Nn * 128];    // layer1 aggregated output
__device__ float g_feat2[Nn * 16];    // layer2 projected features
__device__ float g_el2[Nn];
__device__ float g_er2[Nn];
__device__ float g_expe2[Ee];
__device__ float g_denom2[Nn];

__device__ __forceinline__ void red_add_v4(float* ptr, float4 v) {
    asm volatile("red.global.add.v4.f32 [%0], {%1,%2,%3,%4};"
                 :: "l"(ptr), "f"(v.x), "f"(v.y), "f"(v.z), "f"(v.w)
                 : "memory");
}

__device__ __forceinline__ float leaky02(float x) {
    return x > 0.f ? x : 0.2f * x;
}

// ---------------- init: zero accumulators, seed output with b2 -------------
__global__ void init_kernel(float* __restrict__ out, const float* __restrict__ b2) {
    int i = blockIdx.x * blockDim.x + threadIdx.x;
    int stride = gridDim.x * blockDim.x;
    for (int k = i; k < Nn * 128; k += stride) g_out1[k] = 0.f;
    for (int k = i; k < Nn * 4; k += stride) g_denom1[k] = 0.f;
    for (int k = i; k < Nn; k += stride) g_denom2[k] = 0.f;
    for (int k = i; k < Nn * 16; k += stride) out[k] = b2[k & 15];
}

// ---------------- GEMM1: feat1 = x @ W1  (100000x128 @ 128x128) ------------
// 256 threads/block, 32 nodes per block. Thread computes 4 nodes x 4 cols.
__global__ void gemm1_kernel(const float* __restrict__ x, const float* __restrict__ W1) {
    __shared__ float xsT[128 * 36];  // transposed x tile [k][node], stride 36 keeps float4 alignment
    int tid = threadIdx.x;
    int nblk = blockIdx.x * 32;

    // load x tile [32 nodes][128 k] transposed into smem
#pragma unroll
    for (int r = 0; r < 4; r++) {
        int fi = tid + r * 256;          // float4 index within tile
        int i = fi >> 5;                 // node 0..31
        int kq = fi & 31;                // float4 index within row
        float4 v = *(const float4*)&x[(nblk + i) * 128 + kq * 4];
        xsT[(kq * 4 + 0) * 36 + i] = v.x;
        xsT[(kq * 4 + 1) * 36 + i] = v.y;
        xsT[(kq * 4 + 2) * 36 + i] = v.z;
        xsT[(kq * 4 + 3) * 36 + i] = v.w;
    }
    __syncthreads();

    int tx = tid & 31;      // col group: cols tx*4 .. tx*4+3
    int ty = tid >> 5;      // node group: nodes ty*4 .. ty*4+3
    int n0 = ty * 4;
    float acc[4][4] = {};
    const float4* W4 = (const float4*)W1;

#pragma unroll 4
    for (int k = 0; k < 128; k++) {
        float4 xv = *(const float4*)&xsT[k * 36 + n0];   // broadcast within warp
        float4 wv = __ldg(&W4[k * 32 + tx]);             // coalesced 512B row
        float xs[4] = {xv.x, xv.y, xv.z, xv.w};
        float ws[4] = {wv.x, wv.y, wv.z, wv.w};
#pragma unroll
        for (int a = 0; a < 4; a++)
#pragma unroll
            for (int b = 0; b < 4; b++)
                acc[a][b] = fmaf(xs[a], ws[b], acc[a][b]);
    }
#pragma unroll
    for (int a = 0; a < 4; a++) {
        float4 o = make_float4(acc[a][0], acc[a][1], acc[a][2], acc[a][3]);
        *(float4*)&g_feat1[(nblk + n0 + a) * 128 + tx * 4] = o;
    }
}

// ---------------- el1/er1 = per-head dot(feat, al/ar), warp per node -------
__global__ void elr1_kernel(const float* __restrict__ al1, const float* __restrict__ ar1) {
    int n = (blockIdx.x * blockDim.x + threadIdx.x) >> 5;
    int lane = threadIdx.x & 31;
    if (n >= Nn) return;
    int head = lane >> 3;
    float4 f = *(const float4*)&g_feat1[n * 128 + lane * 4];
    float4 a = *(const float4*)&al1[lane * 4];
    float4 r = *(const float4*)&ar1[lane * 4];
    float el = f.x * a.x + f.y * a.y + f.z * a.z + f.w * a.w;
    float er = f.x * r.x + f.y * r.y + f.z * r.z + f.w * r.w;
    el += __shfl_down_sync(0xffffffffu, el, 4);
    er += __shfl_down_sync(0xffffffffu, er, 4);
    el += __shfl_down_sync(0xffffffffu, el, 2);
    er += __shfl_down_sync(0xffffffffu, er, 2);
    el += __shfl_down_sync(0xffffffffu, el, 1);
    er += __shfl_down_sync(0xffffffffu, er, 1);
    if ((lane & 7) == 0) {
        g_el1[n * 4 + head] = el;
        g_er1[n * 4 + head] = er;
    }
}

// ---------------- edge pass A: expe1 + denom1 (thread per edge) ------------
// No max-subtraction: el+er has sigma ~0.8, exp() is safe in fp32 and the
// softmax is mathematically identical.
__global__ void edgeA_kernel(const int* __restrict__ src, const int* __restrict__ dst) {
    int e = blockIdx.x * blockDim.x + threadIdx.x;
    if (e >= Ee) return;
    int s = src[e], d = dst[e];
    float4 el = *(const float4*)&g_el1[s * 4];
    float4 er = *(const float4*)&g_er1[d * 4];
    float4 v;
    v.x = __expf(leaky02(el.x + er.x));
    v.y = __expf(leaky02(el.y + er.y));
    v.z = __expf(leaky02(el.z + er.z));
    v.w = __expf(leaky02(el.w + er.w));
    *(float4*)&g_expe1[e * 4] = v;
    red_add_v4(&g_denom1[d * 4], v);
}

// ---------------- edge pass B: out1[dst] += feat1[src] * alpha -------------
// Warp per edge: lane i handles one float4 (coalesced 512B gather + v4 RED).
__global__ void scatterB_kernel(const int* __restrict__ src, const int* __restrict__ dst) {
    int e = (blockIdx.x * blockDim.x + threadIdx.x) >> 5;
    if (e >= Ee) return;
    int lane = threadIdx.x & 31;
    int s = __ldg(&src[e]);
    int d = __ldg(&dst[e]);
    float a4 = 0.f;
    if (lane < 4)
        a4 = g_expe1[e * 4 + lane] * __frcp_rn(g_denom1[d * 4 + lane]);
    float alpha = __shfl_sync(0xffffffffu, a4, lane >> 3);  // head = lane/8
    float4 f = *(const float4*)&g_feat1[s * 128 + lane * 4];
    f.x *= alpha; f.y *= alpha; f.z *= alpha; f.w *= alpha;
    red_add_v4(&g_out1[d * 128 + lane * 4], f);
}

// ---------------- mid: +b1, head-mean, relu, GEMM2, el2/er2 (warp/node) ----
__global__ void mid_kernel(const float* __restrict__ b1, const float* __restrict__ W2,
                           const float* __restrict__ al2, const float* __restrict__ ar2) {
    int n = (blockIdx.x * blockDim.x + threadIdx.x) >> 5;
    int lane = threadIdx.x & 31;  // = feature dim d (0..31)
    if (n >= Nn) return;
    float s = 0.f;
#pragma unroll
    for (int h = 0; h < 4; h++)
        s += g_out1[n * 128 + h * 32 + lane] + b1[h * 32 + lane];
    float hv = fmaxf(0.25f * s, 0.f);
    // feat2[j] = sum_d hv_d * W2[d][j]
    float p[16];
#pragma unroll
    for (int j = 0; j < 16; j++) p[j] = hv * W2[lane * 16 + j];
#pragma unroll
    for (int o = 16; o >= 1; o >>= 1)
#pragma unroll
        for (int j = 0; j < 16; j++)
            p[j] += __shfl_xor_sync(0xffffffffu, p[j], o);
    if (lane < 16) g_feat2[n * 16 + lane] = p[lane];
    if (lane == 0) {
        float el = 0.f, er = 0.f;
#pragma unroll
        for (int j = 0; j < 16; j++) {
            el = fmaf(p[j], al2[j], el);
            er = fmaf(p[j], ar2[j], er);
        }
        g_el2[n] = el;
        g_er2[n] = er;
    }
}

// ---------------- edge pass C: expe2 + denom2 ------------------------------
__global__ void edgeC_kernel(const int* __restrict__ src, const int* __restrict__ dst) {
    int e = blockIdx.x * blockDim.x + threadIdx.x;
    if (e >= Ee) return;
    int s = src[e], d = dst[e];
    float ex = __expf(leaky02(g_el2[s] + g_er2[d]));
    g_expe2[e] = ex;
    atomicAdd(&g_denom2[d], ex);
}

// ---------------- edge pass D: out[dst] += feat2[src] * alpha2 -------------
// 4 threads per edge, each one float4 + v4 RED.
__global__ void scatterD_kernel(const int* __restrict__ src, const int* __restrict__ dst,
                                float* __restrict__ out) {
    int t = blockIdx.x * blockDim.x + threadIdx.x;
    int e = t >> 2;
    if (e >= Ee) return;
    int c = (t & 3) * 4;
    int s = src[e], d = dst[e];
    float alpha = g_expe2[e] * __frcp_rn(g_denom2[d]);
    float4 f = *(const float4*)&g_feat2[s * 16 + c];
    f.x *= alpha; f.y *= alpha; f.z *= alpha; f.w *= alpha;
    red_add_v4(&out[d * 16 + c], f);
}

// ---------------- launch ----------------------------------------------------
extern "C" void kernel_launch(void* const* d_in, const int* in_sizes, int n_in,
                              void* d_out, int out_size) {
    const float* x   = (const float*)d_in[0];
    const int*   src = (const int*)d_in[1];
    const int*   dst = (const int*)d_in[2];
    const float* W1  = (const float*)d_in[3];
    const float* al1 = (const float*)d_in[4];
    const float* ar1 = (const float*)d_in[5];
    const float* b1  = (const float*)d_in[6];
    const float* W2  = (const float*)d_in[7];
    const float* al2 = (const float*)d_in[8];
    const float* ar2 = (const float*)d_in[9];
    const float* b2  = (const float*)d_in[10];
    float* out = (float*)d_out;

    init_kernel<<<1024, 256>>>(out, b2);
    gemm1_kernel<<<Nn / 32, 256>>>(x, W1);                    // 3125 blocks
    elr1_kernel<<<(Nn * 32 + 255) / 256, 256>>>(al1, ar1);
    edgeA_kernel<<<(Ee + 255) / 256, 256>>>(src, dst);
    scatterB_kernel<<<Ee / 8, 256>>>(src, dst);               // warp per edge
    mid_kernel<<<(Nn * 32 + 255) / 256, 256>>>(b1, W2, al2, ar2);
    edgeC_kernel<<<(Ee + 255) / 256, 256>>>(src, dst);
    scatterD_kernel<<<(Ee * 4 + 255) / 256, 256>>>(src, dst, out);
}

// round 6
// speedup vs baseline: 1.4304x; 1.4304x over previous
#include <cuda_runtime.h>

#define Nn 100000
#define Ee 1600000
#define NB 391            // ceil(Nn/256) scan blocks

// ---------------- scratch (device globals; allocation-free) ----------------
__device__ float g_feat1[Nn * 128];   // layer1 projected features [N,4,32]
__device__ float g_el1[Nn * 4];
__device__ float g_er1[Nn * 4];
__device__ float g_feat2[Nn * 16];    // layer2 projected features
__device__ float g_el2[Nn];
__device__ float g_er2[Nn];
// CSR by dst
__device__ int g_counts[Nn];
__device__ int g_offs[Nn];
__device__ int g_cursor[Nn];
__device__ int g_bsums[NB];
__device__ int g_csr_src[Ee];

__device__ __forceinline__ float leaky02(float x) {
    return x > 0.f ? x : 0.2f * x;
}

// ---------------- init: zero CSR counts ------------------------------------
__global__ void init_kernel() {
    int i = blockIdx.x * blockDim.x + threadIdx.x;
    if (i < Nn) g_counts[i] = 0;
}

// ---------------- GEMM1 + el/er epilogue -----------------------------------
// feat1 = x @ W1 (100000x128 @ 128x128); then el/er per head reduced in-warp.
__global__ void gemm1_kernel(const float* __restrict__ x, const float* __restrict__ W1,
                             const float* __restrict__ al1, const float* __restrict__ ar1) {
    __shared__ float xsT[128 * 36];
    int tid = threadIdx.x;
    int nblk = blockIdx.x * 32;

#pragma unroll
    for (int r = 0; r < 4; r++) {
        int fi = tid + r * 256;
        int i = fi >> 5;
        int kq = fi & 31;
        float4 v = *(const float4*)&x[(nblk + i) * 128 + kq * 4];
        xsT[(kq * 4 + 0) * 36 + i] = v.x;
        xsT[(kq * 4 + 1) * 36 + i] = v.y;
        xsT[(kq * 4 + 2) * 36 + i] = v.z;
        xsT[(kq * 4 + 3) * 36 + i] = v.w;
    }
    __syncthreads();

    int tx = tid & 31;      // lane; col group tx*4..tx*4+3
    int ty = tid >> 5;      // warp; node group ty*4..ty*4+3
    int n0 = ty * 4;
    float acc[4][4] = {};
    const float4* W4 = (const float4*)W1;

#pragma unroll 4
    for (int k = 0; k < 128; k++) {
        float4 xv = *(const float4*)&xsT[k * 36 + n0];
        float4 wv = __ldg(&W4[k * 32 + tx]);
        float xs[4] = {xv.x, xv.y, xv.z, xv.w};
        float ws[4] = {wv.x, wv.y, wv.z, wv.w};
#pragma unroll
        for (int a = 0; a < 4; a++)
#pragma unroll
            for (int b = 0; b < 4; b++)
                acc[a][b] = fmaf(xs[a], ws[b], acc[a][b]);
    }
#pragma unroll
    for (int a = 0; a < 4; a++) {
        float4 o = make_float4(acc[a][0], acc[a][1], acc[a][2], acc[a][3]);
        *(float4*)&g_feat1[(nblk + n0 + a) * 128 + tx * 4] = o;
    }

    // epilogue: el/er. col = tx*4+b, head = tx>>3; reduce over 8 lanes of head group.
    float4 av = __ldg(&((const float4*)al1)[tx]);
    float4 rv = __ldg(&((const float4*)ar1)[tx]);
    int head = tx >> 3;
#pragma unroll
    for (int a = 0; a < 4; a++) {
        float el = acc[a][0] * av.x + acc[a][1] * av.y + acc[a][2] * av.z + acc[a][3] * av.w;
        float er = acc[a][0] * rv.x + acc[a][1] * rv.y + acc[a][2] * rv.z + acc[a][3] * rv.w;
        el += __shfl_xor_sync(0xffffffffu, el, 1);
        er += __shfl_xor_sync(0xffffffffu, er, 1);
        el += __shfl_xor_sync(0xffffffffu, el, 2);
        er += __shfl_xor_sync(0xffffffffu, er, 2);
        el += __shfl_xor_sync(0xffffffffu, el, 4);
        er += __shfl_xor_sync(0xffffffffu, er, 4);
        if ((tx & 7) == 0) {
            int n = nblk + n0 + a;
            g_el1[n * 4 + head] = el;
            g_er1[n * 4 + head] = er;
        }
    }
}

// ---------------- CSR build -------------------------------------------------
__global__ void hist_kernel(const int* __restrict__ dst) {
    int e = blockIdx.x * blockDim.x + threadIdx.x;
    if (e < Ee) atomicAdd(&g_counts[dst[e]], 1);
}

__global__ void scan_block_kernel() {
    __shared__ int sh[256];
    int t = threadIdx.x;
    int i = blockIdx.x * 256 + t;
    int v = (i < Nn) ? g_counts[i] : 0;
    sh[t] = v;
    __syncthreads();
    for (int off = 1; off < 256; off <<= 1) {
        int add = (t >= off) ? sh[t - off] : 0;
        __syncthreads();
        sh[t] += add;
        __syncthreads();
    }
    if (i < Nn) g_offs[i] = sh[t] - v;        // exclusive within block
    if (t == 255) g_bsums[blockIdx.x] = sh[t];
}

__global__ void scan_sums_kernel() {
    __shared__ int sh[512];
    int t = threadIdx.x;
    int v = (t < NB) ? g_bsums[t] : 0;
    sh[t] = v;
    __syncthreads();
    for (int off = 1; off < 512; off <<= 1) {
        int add = (t >= off) ? sh[t - off] : 0;
        __syncthreads();
        sh[t] += add;
        __syncthreads();
    }
    if (t < NB) g_bsums[t] = sh[t] - v;       // exclusive
}

__global__ void scan_add_kernel() {
    int i = blockIdx.x * 256 + threadIdx.x;
    if (i < Nn) {
        int o = g_offs[i] + g_bsums[i >> 8];
        g_offs[i] = o;
        g_cursor[i] = o;
    }
}

__global__ void fill_kernel(const int* __restrict__ src, const int* __restrict__ dst) {
    int e = blockIdx.x * blockDim.x + threadIdx.x;
    if (e < Ee) {
        int s = src[e];
        int p = atomicAdd(&g_cursor[dst[e]], 1);
        g_csr_src[p] = s;
    }
}

// ---------------- agg1: fused softmax+aggregate+mid (warp per dst node) ----
// Produces feat2, el2, er2 directly.
__global__ void agg1_kernel(const float* __restrict__ b1, const float* __restrict__ W2,
                            const float* __restrict__ al2, const float* __restrict__ ar2) {
    int n = (blockIdx.x * blockDim.x + threadIdx.x) >> 5;
    int lane = threadIdx.x & 31;
    if (n >= Nn) return;
    int head = lane >> 3;
    int start = g_offs[n];
    int end = start + g_counts[n];
    float er = g_er1[n * 4 + head];
    float denom = 0.f;
    float4 acc = make_float4(0.f, 0.f, 0.f, 0.f);

#pragma unroll 4
    for (int p = start; p < end; p++) {
        int s = g_csr_src[p];                       // warp-broadcast load
        float el = g_el1[s * 4 + head];
        float ex = __expf(leaky02(el + er));
        denom += ex;
        float4 f = *(const float4*)&g_feat1[s * 128 + lane * 4];  // coalesced 512B
        acc.x = fmaf(ex, f.x, acc.x);
        acc.y = fmaf(ex, f.y, acc.y);
        acc.z = fmaf(ex, f.z, acc.z);
        acc.w = fmaf(ex, f.w, acc.w);
    }
    float inv = (denom > 0.f) ? __frcp_rn(denom) : 0.f;
    float4 bv = *(const float4*)&b1[lane * 4];
    float y[4] = {fmaf(acc.x, inv, bv.x), fmaf(acc.y, inv, bv.y),
                  fmaf(acc.z, inv, bv.z), fmaf(acc.w, inv, bv.w)};
    // mean over the 4 heads: lanes {L, L^8, L^16, L^24}
#pragma unroll
    for (int c = 0; c < 4; c++) {
        y[c] += __shfl_xor_sync(0xffffffffu, y[c], 8);
        y[c] += __shfl_xor_sync(0xffffffffu, y[c], 16);
    }
    float hv[4];
#pragma unroll
    for (int c = 0; c < 4; c++) hv[c] = fmaxf(0.25f * y[c], 0.f);
    // lane L holds hv for dims (L&7)*4..+3 (replicated across head groups)

    int d0 = (lane & 7) * 4;
    float p16[16] = {};
#pragma unroll
    for (int c = 0; c < 4; c++) {
        float h = hv[c];
        const float4* wrow = (const float4*)&W2[(d0 + c) * 16];
#pragma unroll
        for (int q = 0; q < 4; q++) {
            float4 w = __ldg(&wrow[q]);
            p16[q * 4 + 0] = fmaf(h, w.x, p16[q * 4 + 0]);
            p16[q * 4 + 1] = fmaf(h, w.y, p16[q * 4 + 1]);
            p16[q * 4 + 2] = fmaf(h, w.z, p16[q * 4 + 2]);
            p16[q * 4 + 3] = fmaf(h, w.w, p16[q * 4 + 3]);
        }
    }
    // reduce across the 8 lanes of each group
#pragma unroll
    for (int o = 1; o <= 4; o <<= 1)
#pragma unroll
        for (int j = 0; j < 16; j++)
            p16[j] += __shfl_xor_sync(0xffffffffu, p16[j], o);
    // every lane now holds full feat2[n][0..15]
    if (lane < 4) {
        float4 o4 = make_float4(p16[lane * 4], p16[lane * 4 + 1],
                                p16[lane * 4 + 2], p16[lane * 4 + 3]);
        *(float4*)&g_feat2[n * 16 + lane * 4] = o4;
    }
    if (lane == 0) {
        float el2 = 0.f, er2 = 0.f;
#pragma unroll
        for (int j = 0; j < 16; j++) {
            el2 = fmaf(p16[j], al2[j], el2);
            er2 = fmaf(p16[j], ar2[j], er2);
        }
        g_el2[n] = el2;
        g_er2[n] = er2;
    }
}

// ---------------- agg2: layer-2 softmax+aggregate (4 lanes per dst node) ---
__global__ void agg2_kernel(const float* __restrict__ b2, float* __restrict__ out) {
    int t = blockIdx.x * blockDim.x + threadIdx.x;
    int n = t >> 2;
    if (n >= Nn) return;
    int c = (t & 3) * 4;
    int start = g_offs[n];
    int end = start + g_counts[n];
    float er = g_er2[n];
    float denom = 0.f;
    float4 acc = make_float4(0.f, 0.f, 0.f, 0.f);
#pragma unroll 4
    for (int p = start; p < end; p++) {
        int s = g_csr_src[p];
        float ex = __expf(leaky02(g_el2[s] + er));
        denom += ex;
        float4 f = *(const float4*)&g_feat2[s * 16 + c];
        acc.x = fmaf(ex, f.x, acc.x);
        acc.y = fmaf(ex, f.y, acc.y);
        acc.z = fmaf(ex, f.z, acc.z);
        acc.w = fmaf(ex, f.w, acc.w);
    }
    float inv = (denom > 0.f) ? __frcp_rn(denom) : 0.f;
    float4 bv = *(const float4*)&b2[c];
    float4 o4 = make_float4(fmaf(acc.x, inv, bv.x), fmaf(acc.y, inv, bv.y),
                            fmaf(acc.z, inv, bv.z), fmaf(acc.w, inv, bv.w));
    *(float4*)&out[n * 16 + c] = o4;
}

// ---------------- launch ----------------------------------------------------
extern "C" void kernel_launch(void* const* d_in, const int* in_sizes, int n_in,
                              void* d_out, int out_size) {
    const float* x   = (const float*)d_in[0];
    const int*   src = (const int*)d_in[1];
    const int*   dst = (const int*)d_in[2];
    const float* W1  = (const float*)d_in[3];
    const float* al1 = (const float*)d_in[4];
    const float* ar1 = (const float*)d_in[5];
    const float* b1  = (const float*)d_in[6];
    const float* W2  = (const float*)d_in[7];
    const float* al2 = (const float*)d_in[8];
    const float* ar2 = (const float*)d_in[9];
    const float* b2  = (const float*)d_in[10];
    float* out = (float*)d_out;

    init_kernel<<<NB, 256>>>();
    hist_kernel<<<(Ee + 255) / 256, 256>>>(dst);
    gemm1_kernel<<<Nn / 32, 256>>>(x, W1, al1, ar1);
    scan_block_kernel<<<NB, 256>>>();
    scan_sums_kernel<<<1, 512>>>();
    scan_add_kernel<<<NB, 256>>>();
    fill_kernel<<<(Ee + 255) / 256, 256>>>(src, dst);
    agg1_kernel<<<(Nn * 32 + 255) / 256, 256>>>(b1, W2, al2, ar2);
    agg2_kernel<<<(Nn * 4 + 255) / 256, 256>>>(b2, out);
}

// round 7
// speedup vs baseline: 1.5097x; 1.0554x over previous
#include <cuda_runtime.h>

#define Nn 100000
#define Ee 1600000
#define NB 391            // ceil(Nn/256) scan blocks

typedef unsigned long long u64;

// ---------------- scratch (device globals; allocation-free) ----------------
__device__ float g_feat1[Nn * 128];   // layer1 projected features [N,4,32]
__device__ float g_el1[Nn * 4];
__device__ float g_er1[Nn * 4];
__device__ float g_feat2[Nn * 16];    // layer2 projected features
__device__ float g_el2[Nn];
__device__ float g_er2[Nn];
// CSR by dst
__device__ int g_counts[Nn];
__device__ int g_offs[Nn];
__device__ int g_cursor[Nn];
__device__ int g_bsums[NB];
__device__ int g_csr_src[Ee];

__device__ __forceinline__ float leaky02(float x) {
    return x > 0.f ? x : 0.2f * x;
}

// packed f32x2 helpers (FFMA2 is PTX-only; ptxas never auto-fuses)
__device__ __forceinline__ u64 dup2(float v) {
    u64 d; asm("mov.b64 %0, {%1, %1};" : "=l"(d) : "f"(v)); return d;
}
__device__ __forceinline__ void fma2(u64& d, u64 a, u64 b) {
    asm("fma.rn.f32x2 %0, %1, %2, %0;" : "+l"(d) : "l"(a), "l"(b));
}
__device__ __forceinline__ void unpack2(float& lo, float& hi, u64 v) {
    asm("mov.b64 {%0, %1}, %2;" : "=f"(lo), "=f"(hi) : "l"(v));
}

// ---------------- init: zero CSR counts ------------------------------------
__global__ void init_kernel() {
    int i = blockIdx.x * blockDim.x + threadIdx.x;
    if (i < Nn) g_counts[i] = 0;
}

// ---------------- GEMM1 + el/er epilogue (f32x2 packed FMA) ----------------
// feat1 = x @ W1 (100000x128 @ 128x128); per-head el/er reduced in-warp.
__global__ void gemm1_kernel(const float* __restrict__ x, const float* __restrict__ W1,
                             const float* __restrict__ al1, const float* __restrict__ ar1) {
    __shared__ float xsT[128 * 36];
    int tid = threadIdx.x;
    int nblk = blockIdx.x * 32;

#pragma unroll
    for (int r = 0; r < 4; r++) {
        int fi = tid + r * 256;
        int i = fi >> 5;
        int kq = fi & 31;
        float4 v = *(const float4*)&x[(nblk + i) * 128 + kq * 4];
        xsT[(kq * 4 + 0) * 36 + i] = v.x;
        xsT[(kq * 4 + 1) * 36 + i] = v.y;
        xsT[(kq * 4 + 2) * 36 + i] = v.z;
        xsT[(kq * 4 + 3) * 36 + i] = v.w;
    }
    __syncthreads();

    int tx = tid & 31;      // lane; col group tx*4..tx*4+3
    int ty = tid >> 5;      // warp; node group ty*4..ty*4+3
    int n0 = ty * 4;
    // accP[g][b]: packed pair over nodes (n0+2g, n0+2g+1), column b
    u64 accP[2][4] = {};
    const float4* W4 = (const float4*)W1;

#pragma unroll 4
    for (int k = 0; k < 128; k++) {
        // A pairs come pre-packed from smem (consecutive nodes contiguous)
        float4 xv = *(const float4*)&xsT[k * 36 + n0];  // warp-broadcast
        u64 a01, a23;
        asm("mov.b64 %0, {%1, %2};" : "=l"(a01) : "f"(xv.x), "f"(xv.y));
        asm("mov.b64 %0, {%1, %2};" : "=l"(a23) : "f"(xv.z), "f"(xv.w));
        float4 wv = __ldg(&W4[k * 32 + tx]);            // coalesced 512B row
        u64 w0 = dup2(wv.x), w1 = dup2(wv.y), w2 = dup2(wv.z), w3 = dup2(wv.w);
        fma2(accP[0][0], a01, w0); fma2(accP[0][1], a01, w1);
        fma2(accP[0][2], a01, w2); fma2(accP[0][3], a01, w3);
        fma2(accP[1][0], a23, w0); fma2(accP[1][1], a23, w1);
        fma2(accP[1][2], a23, w2); fma2(accP[1][3], a23, w3);
    }

    // unpack to per-node scalars
    float acc[4][4];
#pragma unroll
    for (int g = 0; g < 2; g++)
#pragma unroll
        for (int b = 0; b < 4; b++)
            unpack2(acc[2 * g][b], acc[2 * g + 1][b], accP[g][b]);

#pragma unroll
    for (int a = 0; a < 4; a++) {
        float4 o = make_float4(acc[a][0], acc[a][1], acc[a][2], acc[a][3]);
        *(float4*)&g_feat1[(nblk + n0 + a) * 128 + tx * 4] = o;
    }

    // epilogue: el/er. col = tx*4+b, head = tx>>3; reduce over 8 lanes of head group.
    float4 av = __ldg(&((const float4*)al1)[tx]);
    float4 rv = __ldg(&((const float4*)ar1)[tx]);
    int head = tx >> 3;
#pragma unroll
    for (int a = 0; a < 4; a++) {
        float el = acc[a][0] * av.x + acc[a][1] * av.y + acc[a][2] * av.z + acc[a][3] * av.w;
        float er = acc[a][0] * rv.x + acc[a][1] * rv.y + acc[a][2] * rv.z + acc[a][3] * rv.w;
        el += __shfl_xor_sync(0xffffffffu, el, 1);
        er += __shfl_xor_sync(0xffffffffu, er, 1);
        el += __shfl_xor_sync(0xffffffffu, el, 2);
        er += __shfl_xor_sync(0xffffffffu, er, 2);
        el += __shfl_xor_sync(0xffffffffu, el, 4);
        er += __shfl_xor_sync(0xffffffffu, er, 4);
        if ((tx & 7) == 0) {
            int n = nblk + n0 + a;
            g_el1[n * 4 + head] = el;
            g_er1[n * 4 + head] = er;
        }
    }
}

// ---------------- CSR build -------------------------------------------------
__global__ void hist_kernel(const int* __restrict__ dst) {
    int e = blockIdx.x * blockDim.x + threadIdx.x;
    if (e < Ee) atomicAdd(&g_counts[dst[e]], 1);
}

__global__ void scan_block_kernel() {
    __shared__ int sh[256];
    int t = threadIdx.x;
    int i = blockIdx.x * 256 + t;
    int v = (i < Nn) ? g_counts[i] : 0;
    sh[t] = v;
    __syncthreads();
    for (int off = 1; off < 256; off <<= 1) {
        int add = (t >= off) ? sh[t - off] : 0;
        __syncthreads();
        sh[t] += add;
        __syncthreads();
    }
    if (i < Nn) g_offs[i] = sh[t] - v;        // exclusive within block
    if (t == 255) g_bsums[blockIdx.x] = sh[t];
}

__global__ void scan_sums_kernel() {
    __shared__ int sh[512];
    int t = threadIdx.x;
    int v = (t < NB) ? g_bsums[t] : 0;
    sh[t] = v;
    __syncthreads();
    for (int off = 1; off < 512; off <<= 1) {
        int add = (t >= off) ? sh[t - off] : 0;
        __syncthreads();
        sh[t] += add;
        __syncthreads();
    }
    if (t < NB) g_bsums[t] = sh[t] - v;       // exclusive
}

__global__ void scan_add_kernel() {
    int i = blockIdx.x * 256 + threadIdx.x;
    if (i < Nn) {
        int o = g_offs[i] + g_bsums[i >> 8];
        g_offs[i] = o;
        g_cursor[i] = o;
    }
}

__global__ void fill_kernel(const int* __restrict__ src, const int* __restrict__ dst) {
    int e = blockIdx.x * blockDim.x + threadIdx.x;
    if (e < Ee) {
        int s = src[e];
        int p = atomicAdd(&g_cursor[dst[e]], 1);
        g_csr_src[p] = s;
    }
}

// ---------------- agg1: fused softmax+aggregate+mid (warp per dst node) ----
// Produces feat2, el2, er2 directly.
__global__ void agg1_kernel(const float* __restrict__ b1, const float* __restrict__ W2,
                            const float* __restrict__ al2, const float* __restrict__ ar2) {
    int n = (blockIdx.x * blockDim.x + threadIdx.x) >> 5;
    int lane = threadIdx.x & 31;
    if (n >= Nn) return;
    int head = lane >> 3;
    int start = g_offs[n];
    int end = start + g_counts[n];
    float er = g_er1[n * 4 + head];
    float denom = 0.f;
    float4 acc = make_float4(0.f, 0.f, 0.f, 0.f);

#pragma unroll 8
    for (int p = start; p < end; p++) {
        int s = __ldg(&g_csr_src[p]);               // warp-broadcast load
        float el = __ldg(&g_el1[s * 4 + head]);
        float ex = __expf(leaky02(el + er));
        denom += ex;
        float4 f = *(const float4*)&g_feat1[s * 128 + lane * 4];  // coalesced 512B
        acc.x = fmaf(ex, f.x, acc.x);
        acc.y = fmaf(ex, f.y, acc.y);
        acc.z = fmaf(ex, f.z, acc.z);
        acc.w = fmaf(ex, f.w, acc.w);
    }
    float inv = (denom > 0.f) ? __frcp_rn(denom) : 0.f;
    float4 bv = *(const float4*)&b1[lane * 4];
    float y[4] = {fmaf(acc.x, inv, bv.x), fmaf(acc.y, inv, bv.y),
                  fmaf(acc.z, inv, bv.z), fmaf(acc.w, inv, bv.w)};
    // mean over the 4 heads: lanes {L, L^8, L^16, L^24}
#pragma unroll
    for (int c = 0; c < 4; c++) {
        y[c] += __shfl_xor_sync(0xffffffffu, y[c], 8);
        y[c] += __shfl_xor_sync(0xffffffffu, y[c], 16);
    }
    float hv[4];
#pragma unroll
    for (int c = 0; c < 4; c++) hv[c] = fmaxf(0.25f * y[c], 0.f);
    // lane L holds hv for dims (L&7)*4..+3 (replicated across head groups)

    int d0 = (lane & 7) * 4;
    float p16[16] = {};
#pragma unroll
    for (int c = 0; c < 4; c++) {
        float h = hv[c];
        const float4* wrow = (const float4*)&W2[(d0 + c) * 16];
#pragma unroll
        for (int q = 0; q < 4; q++) {
            float4 w = __ldg(&wrow[q]);
            p16[q * 4 + 0] = fmaf(h, w.x, p16[q * 4 + 0]);
            p16[q * 4 + 1] = fmaf(h, w.y, p16[q * 4 + 1]);
            p16[q * 4 + 2] = fmaf(h, w.z, p16[q * 4 + 2]);
            p16[q * 4 + 3] = fmaf(h, w.w, p16[q * 4 + 3]);
        }
    }
    // reduce across the 8 lanes of each group
#pragma unroll
    for (int o = 1; o <= 4; o <<= 1)
#pragma unroll
        for (int j = 0; j < 16; j++)
            p16[j] += __shfl_xor_sync(0xffffffffu, p16[j], o);
    // every lane now holds full feat2[n][0..15]
    if (lane < 4) {
        float4 o4 = make_float4(p16[lane * 4], p16[lane * 4 + 1],
                                p16[lane * 4 + 2], p16[lane * 4 + 3]);
        *(float4*)&g_feat2[n * 16 + lane * 4] = o4;
    }
    if (lane == 0) {
        float el2 = 0.f, er2 = 0.f;
#pragma unroll
        for (int j = 0; j < 16; j++) {
            el2 = fmaf(p16[j], al2[j], el2);
            er2 = fmaf(p16[j], ar2[j], er2);
        }
        g_el2[n] = el2;
        g_er2[n] = er2;
    }
}

// ---------------- agg2: layer-2 softmax+aggregate (4 lanes per dst node) ---
__global__ void agg2_kernel(const float* __restrict__ b2, float* __restrict__ out) {
    int t = blockIdx.x * blockDim.x + threadIdx.x;
    int n = t >> 2;
    if (n >= Nn) return;
    int c = (t & 3) * 4;
    int start = g_offs[n];
    int end = start + g_counts[n];
    float er = g_er2[n];
    float denom = 0.f;
    float4 acc = make_float4(0.f, 0.f, 0.f, 0.f);
#pragma unroll 8
    for (int p = start; p < end; p++) {
        int s = __ldg(&g_csr_src[p]);
        float ex = __expf(leaky02(__ldg(&g_el2[s]) + er));
        denom += ex;
        float4 f = *(const float4*)&g_feat2[s * 16 + c];
        acc.x = fmaf(ex, f.x, acc.x);
        acc.y = fmaf(ex, f.y, acc.y);
        acc.z = fmaf(ex, f.z, acc.z);
        acc.w = fmaf(ex, f.w, acc.w);
    }
    float inv = (denom > 0.f) ? __frcp_rn(denom) : 0.f;
    float4 bv = *(const float4*)&b2[c];
    float4 o4 = make_float4(fmaf(acc.x, inv, bv.x), fmaf(acc.y, inv, bv.y),
                            fmaf(acc.z, inv, bv.z), fmaf(acc.w, inv, bv.w));
    *(float4*)&out[n * 16 + c] = o4;
}

// ---------------- launch ----------------------------------------------------
extern "C" void kernel_launch(void* const* d_in, const int* in_sizes, int n_in,
                              void* d_out, int out_size) {
    const float* x   = (const float*)d_in[0];
    const int*   src = (const int*)d_in[1];
    const int*   dst = (const int*)d_in[2];
    const float* W1  = (const float*)d_in[3];
    const float* al1 = (const float*)d_in[4];
    const float* ar1 = (const float*)d_in[5];
    const float* b1  = (const float*)d_in[6];
    const float* W2  = (const float*)d_in[7];
    const float* al2 = (const float*)d_in[8];
    const float* ar2 = (const float*)d_in[9];
    const float* b2  = (const float*)d_in[10];
    float* out = (float*)d_out;

    init_kernel<<<NB, 256>>>();
    hist_kernel<<<(Ee + 255) / 256, 256>>>(dst);
    gemm1_kernel<<<Nn / 32, 256>>>(x, W1, al1, ar1);
    scan_block_kernel<<<NB, 256>>>();
    scan_sums_kernel<<<1, 512>>>();
    scan_add_kernel<<<NB, 256>>>();
    fill_kernel<<<(Ee + 255) / 256, 256>>>(src, dst);
    agg1_kernel<<<(Nn * 32 + 255) / 256, 256>>>(b1, W2, al2, ar2);
    agg2_kernel<<<(Nn * 4 + 255) / 256, 256>>>(b2, out);
}